// round 16
// baseline (speedup 1.0000x reference)
#include <cuda_runtime.h>
#include <cstdint>

#define DFEAT 48
#define NCG   12                       // float4 column-groups per row (48/4)
#define HROWS 128                      // rows per pipeline half
#define NWALK 32                       // row-walkers per column-group
#define WALKR (HROWS / NWALK)          // 4 rows per walker
#define MAIN_THREADS (NCG * NWALK)     // 384
#define BLOCKS_PER_SM 4

#define HALF_BYTES  (HROWS * DFEAT * 4)            // 24576 per buffer
#define SMEM_FT(b)  ((b) * HALF_BYTES)             // 2 tile buffers
#define SMEM_W_OFF  (2 * HALF_BYTES)               // w[2][HROWS]
#define SMEM_S_OFF  (SMEM_W_OFF + 2 * HROWS * 4)   // s[2][HROWS]
#define SMEM_MB_OFF (SMEM_S_OFF + 2 * HROWS * 4)   // mbar[2]
#define SMEM_TOTAL  (SMEM_MB_OFF + 32)

// Per-node softmax denominators (N = 50000 here; padded)
__device__ float g_denom[65536];

// Edge-parallel denom accumulation (8 consecutive edges/thread, float4/int4
// loads, run-aggregated atomics on sorted sids) + fused grid-stride zeroing
// of the output buffer. Triggers PDL immediately so k_main's independent
// prologue (TMA issue + exp staging) overlaps this kernel.
__global__ void k_exp(const float* __restrict__ a,
                      const int* __restrict__ seg, int E,
                      float4* __restrict__ out4, int out_n4) {
#if __CUDA_ARCH__ >= 900
    cudaTriggerProgrammaticLaunchCompletion();
#endif
    int t = blockIdx.x * blockDim.x + threadIdx.x;

    // Fused: zero the output (harness poisons it to 0xAA)
    int nthreads = gridDim.x * blockDim.x;
    for (int i = t; i < out_n4; i += nthreads)
        out4[i] = make_float4(0.f, 0.f, 0.f, 0.f);

    int e0 = t * 8;
    if (e0 >= E) return;

    if (e0 + 8 <= E) {
        float acc = 0.0f;
        int cur = -1;
        #pragma unroll
        for (int h = 0; h < 2; h++) {
            float4 av = *(const float4*)(a + e0 + h * 4);
            int4   sv = *(const int4*)(seg + e0 + h * 4);
            float ex[4] = {__expf(av.x), __expf(av.y), __expf(av.z), __expf(av.w)};
            int   sd[4] = {sv.x, sv.y, sv.z, sv.w};
            #pragma unroll
            for (int k = 0; k < 4; k++) {
                if (sd[k] != cur) {
                    if (cur >= 0) atomicAdd(&g_denom[cur], acc);
                    acc = 0.0f; cur = sd[k];
                }
                acc += ex[k];
            }
        }
        atomicAdd(&g_denom[cur], acc);
    } else {
        for (int e = e0; e < E; e++)
            atomicAdd(&g_denom[seg[e]], __expf(a[e]));
    }
}

__device__ __forceinline__ uint32_t smem_u32(const void* p) {
    return (uint32_t)__cvta_generic_to_shared(p);
}
__device__ __forceinline__ void mbar_init(uint32_t mbar, uint32_t count) {
    asm volatile("mbarrier.init.shared.b64 [%0], %1;" :: "r"(mbar), "r"(count) : "memory");
}
__device__ __forceinline__ void mbar_expect_tx(uint32_t mbar, uint32_t bytes) {
    asm volatile("mbarrier.arrive.expect_tx.shared.b64 _, [%0], %1;"
                 :: "r"(mbar), "r"(bytes) : "memory");
}
// Bulk copy with L2 evict_first hint: ft is streamed exactly once, so its
// sectors are first eviction candidates, keeping out/a/seg/denom resident.
__device__ __forceinline__ void bulk_g2s_stream(uint32_t dst_smem, const void* src_gmem,
                                                uint32_t bytes, uint32_t mbar) {
    uint64_t policy;
    asm volatile("createpolicy.fractional.L2::evict_first.b64 %0, 1.0;" : "=l"(policy));
    asm volatile(
        "cp.async.bulk.shared::cta.global.mbarrier::complete_tx::bytes.L2::cache_hint "
        "[%0], [%1], %2, [%3], %4;"
        :: "r"(dst_smem), "l"(src_gmem), "r"(bytes), "r"(mbar), "l"(policy) : "memory");
}
__device__ __forceinline__ void mbar_wait(uint32_t mbar, uint32_t parity) {
    asm volatile(
        "{\n\t"
        ".reg .pred P;\n\t"
        "W%=:\n\t"
        "mbarrier.try_wait.parity.shared::cta.b64 P, [%0], %1;\n\t"
        "@!P bra W%=;\n\t"
        "}"
        :: "r"(mbar), "r"(parity) : "memory");
}

// Vectorized global reduction: one instruction instead of 4 scalar REDs.
__device__ __forceinline__ void red_add_v4(float* p, float4 v) {
    asm volatile("red.global.add.v4.f32 [%0], {%1, %2, %3, %4};"
                 :: "l"(p), "f"(v.x), "f"(v.y), "f"(v.z), "f"(v.w) : "memory");
}

// Medium-persistent main pass: grid = 4 x SMs. Each block owns a contiguous
// run of 128-row halves with TWO 24KB buffers: in iteration i it issues the
// TMA for half i+1 into buf^1 and stages that half's weights, then waits on
// buf's mbarrier and computes — a bulk copy is always outstanding per block,
// independent of cross-block phase alignment. Prologue + PDL grid sync paid
// once per block. Compute: 12 float4-column-groups x 32 row-walkers (4 rows
// each) from smem; red.v4 flush only at segment boundaries (seg is sorted).
__global__ void __launch_bounds__(MAIN_THREADS, BLOCKS_PER_SM)
k_main(const float* __restrict__ a,
       const float* __restrict__ ft,
       const int* __restrict__ seg,
       float* __restrict__ out, int E) {
    extern __shared__ __align__(128) char smem[];
    float* w_all = (float*)(smem + SMEM_W_OFF);
    int*   s_all = (int*)(smem + SMEM_S_OFF);
    uint32_t mb0 = smem_u32(smem + SMEM_MB_OFF);

    int tid = threadIdx.x;
    int nh = (E + HROWS - 1) / HROWS;
    int per = (nh + gridDim.x - 1) / gridDim.x;
    int h0 = blockIdx.x * per;
    int h1 = min(h0 + per, nh);

    if (tid == 0) { mbar_init(mb0, 1); mbar_init(mb0 + 8, 1); }
    __syncthreads();
    if (h0 >= h1) {
#if __CUDA_ARCH__ >= 900
        cudaGridDependencySynchronize();
#endif
        return;
    }

    bool used_tma[2] = {false, false};

    // Issue TMA + stage ex/sid for half h into buffer b (no denom needed).
    // Weight division applied separately (post grid-sync / steady state).
    auto stage_pre = [&](int h, int b) {
        int base = h * HROWS;
        bool full2 = (base + HROWS <= E);
        if (full2) {
            if (tid == 0) {
                uint32_t mb = mb0 + b * 8;
                mbar_expect_tx(mb, HALF_BYTES);
                bulk_g2s_stream(smem_u32(smem + SMEM_FT(b)),
                                ft + (size_t)base * DFEAT, HALF_BYTES, mb);
            }
        } else {
            const float4* ft4 = (const float4*)ft;
            float4* s_ft = (float4*)(smem + SMEM_FT(b));
            for (int i = tid; i < HROWS * NCG; i += MAIN_THREADS) {
                int row = base + i / NCG;
                s_ft[i] = (row < E) ? ft4[(size_t)row * NCG + (i % NCG)]
                                    : make_float4(0.f, 0.f, 0.f, 0.f);
            }
        }
        used_tma[b] = full2;
    };

    // Prologue: first half — TMA + ex/sid before grid sync, divide after.
    stage_pre(h0, 0);
    float ex0 = 0.0f; int sid0 = -1;
    if (tid < HROWS) {
        int e = h0 * HROWS + tid;
        if (e < E) { sid0 = seg[e]; ex0 = __expf(a[e]); }
        s_all[tid] = sid0;
    }
#if __CUDA_ARCH__ >= 900
    cudaGridDependencySynchronize();   // k_exp (denom + out zero) complete
#endif
    if (tid < HROWS)
        w_all[tid] = (sid0 >= 0) ? __fdividef(ex0, g_denom[sid0]) : 0.0f;
    __syncthreads();

    int cg = tid % NCG;            // float4 column group (0..11)
    int y  = tid / NCG;            // walker id (0..31)
    int j0 = y * WALKR;

    int ph[2] = {0, 0};
    int buf = 0;

    for (int h = h0; h < h1; h++) {
        // Stage next half into buf^1 (TMA + full weights; denom is ready).
        if (h + 1 < h1) {
            int nb = buf ^ 1;
            stage_pre(h + 1, nb);
            if (tid < HROWS) {
                int e = (h + 1) * HROWS + tid;
                float w = 0.0f; int sid = -1;
                if (e < E) {
                    sid = seg[e];
                    w = __fdividef(__expf(a[e]), g_denom[sid]);
                }
                w_all[nb * HROWS + tid] = w;
                s_all[nb * HROWS + tid] = sid;
            }
        }

        if (used_tma[buf]) { mbar_wait(mb0 + buf * 8, ph[buf]); ph[buf] ^= 1; }

        const float4* s_ft = (const float4*)(smem + SMEM_FT(buf));
        const float*  w_s  = w_all + buf * HROWS;
        const int*    s_s  = s_all + buf * HROWS;

        int    cur = s_s[j0];
        float4 acc = make_float4(0.f, 0.f, 0.f, 0.f);

        #pragma unroll
        for (int k = 0; k < WALKR; k++) {
            int j = j0 + k;
            int    sid = s_s[j];
            float  w   = w_s[j];
            float4 v   = s_ft[j * NCG + cg];
            if (sid != cur) {
                if (cur >= 0) red_add_v4(out + (size_t)cur * DFEAT + cg * 4, acc);
                acc = make_float4(0.f, 0.f, 0.f, 0.f);
                cur = sid;
            }
            acc.x += w * v.x;
            acc.y += w * v.y;
            acc.z += w * v.z;
            acc.w += w * v.w;
        }
        if (cur >= 0) red_add_v4(out + (size_t)cur * DFEAT + cg * 4, acc);

        __syncthreads();           // all reads of buf done before its refill
        buf ^= 1;
    }
}

extern "C" void kernel_launch(void* const* d_in, const int* in_sizes, int n_in,
                              void* d_out, int out_size) {
    const float* a   = (const float*)d_in[0];
    const float* ft  = (const float*)d_in[1];
    const int*   seg = (const int*)d_in[2];
    float* out = (float*)d_out;

    int E = in_sizes[0];

    // Zero denominators directly on the device symbol (no kernel launch).
    void* denom_ptr = nullptr;
    cudaGetSymbolAddress(&denom_ptr, g_denom);
    cudaMemsetAsync(denom_ptr, 0, sizeof(g_denom));

    // k_exp also zeroes the output buffer (fused).
    int e8 = (E + 7) / 8;
    k_exp<<<(e8 + 255) / 256, 256>>>(a, seg, E, (float4*)out, out_size / 4);

    int sm_count = 148;
    cudaDeviceGetAttribute(&sm_count, cudaDevAttrMultiProcessorCount, 0);

    cudaFuncSetAttribute(k_main, cudaFuncAttributeMaxDynamicSharedMemorySize,
                         SMEM_TOTAL);

    // PDL launch: k_main's prologue overlaps k_exp.
    cudaLaunchConfig_t cfg = {};
    cfg.gridDim = dim3(sm_count * BLOCKS_PER_SM);
    cfg.blockDim = dim3(MAIN_THREADS);
    cfg.dynamicSmemBytes = SMEM_TOTAL;
    cudaLaunchAttribute attrs[1];
    attrs[0].id = cudaLaunchAttributeProgrammaticStreamSerialization;
    attrs[0].val.programmaticStreamSerializationAllowed = 1;
    cfg.attrs = attrs;
    cfg.numAttrs = 1;
    cudaLaunchKernelEx(&cfg, k_main, a, ft, seg, out, E);
}

// round 17
// speedup vs baseline: 1.1678x; 1.1678x over previous
#include <cuda_runtime.h>
#include <cstdint>

#define DFEAT 48
#define NCG   12                       // float4 column-groups per row (48/4)
#define CHUNK 256                      // edges per block in k_main
#define NWALK 32                       // row-walkers per column-group
#define WALKR (CHUNK / NWALK)          // 8 rows per walker
#define MAIN_THREADS (NCG * NWALK)     // 384

#define HALF_ROWS     (CHUNK / 2)                  // 128 rows per TMA half
#define HALF_BYTES    (HALF_ROWS * DFEAT * 4)      // 24576
#define FT_TILE_BYTES (CHUNK * DFEAT * 4)          // 49152 (48KB)
#define SMEM_W_OFF    FT_TILE_BYTES                // w_s: CHUNK floats
#define SMEM_S_OFF    (FT_TILE_BYTES + CHUNK * 4)  // s_s: CHUNK ints
#define SMEM_MBAR_OFF (FT_TILE_BYTES + CHUNK * 8)  // mbar[2]
#define SMEM_TOTAL    (SMEM_MBAR_OFF + 32)

// Per-node softmax denominators (N = 50000 here; padded)
__device__ float g_denom[65536];

// Edge-parallel denom accumulation (8 consecutive edges/thread, float4/int4
// loads, run-aggregated atomics on sorted sids) + fused grid-stride zeroing
// of the output buffer. Triggers PDL immediately so k_main's independent
// prologue (TMA issue + exp staging) overlaps this kernel.
__global__ void k_exp(const float* __restrict__ a,
                      const int* __restrict__ seg, int E,
                      float4* __restrict__ out4, int out_n4) {
#if __CUDA_ARCH__ >= 900
    cudaTriggerProgrammaticLaunchCompletion();
#endif
    int t = blockIdx.x * blockDim.x + threadIdx.x;

    // Fused: zero the output (harness poisons it to 0xAA)
    int nthreads = gridDim.x * blockDim.x;
    for (int i = t; i < out_n4; i += nthreads)
        out4[i] = make_float4(0.f, 0.f, 0.f, 0.f);

    int e0 = t * 8;
    if (e0 >= E) return;

    if (e0 + 8 <= E) {
        float acc = 0.0f;
        int cur = -1;
        #pragma unroll
        for (int h = 0; h < 2; h++) {
            float4 av = *(const float4*)(a + e0 + h * 4);
            int4   sv = *(const int4*)(seg + e0 + h * 4);
            float ex[4] = {__expf(av.x), __expf(av.y), __expf(av.z), __expf(av.w)};
            int   sd[4] = {sv.x, sv.y, sv.z, sv.w};
            #pragma unroll
            for (int k = 0; k < 4; k++) {
                if (sd[k] != cur) {
                    if (cur >= 0) atomicAdd(&g_denom[cur], acc);
                    acc = 0.0f; cur = sd[k];
                }
                acc += ex[k];
            }
        }
        atomicAdd(&g_denom[cur], acc);
    } else {
        for (int e = e0; e < E; e++)
            atomicAdd(&g_denom[seg[e]], __expf(a[e]));
    }
}

__device__ __forceinline__ uint32_t smem_u32(const void* p) {
    return (uint32_t)__cvta_generic_to_shared(p);
}
__device__ __forceinline__ void mbar_init(uint32_t mbar, uint32_t count) {
    asm volatile("mbarrier.init.shared.b64 [%0], %1;" :: "r"(mbar), "r"(count) : "memory");
}
__device__ __forceinline__ void mbar_expect_tx(uint32_t mbar, uint32_t bytes) {
    asm volatile("mbarrier.arrive.expect_tx.shared.b64 _, [%0], %1;"
                 :: "r"(mbar), "r"(bytes) : "memory");
}
// Bulk copy with L2 evict_first hint: ft is streamed exactly once, so its
// sectors should be first eviction candidates, keeping out/a/seg/denom
// resident in L2 (out lines are hit by ~6M red.v4 ops).
__device__ __forceinline__ void bulk_g2s_stream(uint32_t dst_smem, const void* src_gmem,
                                                uint32_t bytes, uint32_t mbar) {
    uint64_t policy;
    asm volatile("createpolicy.fractional.L2::evict_first.b64 %0, 1.0;" : "=l"(policy));
    asm volatile(
        "cp.async.bulk.shared::cta.global.mbarrier::complete_tx::bytes.L2::cache_hint "
        "[%0], [%1], %2, [%3], %4;"
        :: "r"(dst_smem), "l"(src_gmem), "r"(bytes), "r"(mbar), "l"(policy) : "memory");
}
__device__ __forceinline__ void mbar_wait(uint32_t mbar, uint32_t parity) {
    asm volatile(
        "{\n\t"
        ".reg .pred P;\n\t"
        "W%=:\n\t"
        "mbarrier.try_wait.parity.shared::cta.b64 P, [%0], %1;\n\t"
        "@!P bra W%=;\n\t"
        "}"
        :: "r"(mbar), "r"(parity) : "memory");
}

// Vectorized global reduction: one instruction instead of 4 scalar REDs.
__device__ __forceinline__ void red_add_v4(float* p, float4 v) {
    asm volatile("red.global.add.v4.f32 [%0], {%1, %2, %3, %4};"
                 :: "l"(p), "f"(v.x), "f"(v.y), "f"(v.z), "f"(v.w) : "memory");
}

// Main pass: block = 256 contiguous edges. Tile split into two 24KB TMA
// copies (evict_first L2 hint) with separate mbarriers: warps consuming
// rows 0-127 wait only on the first half. 4 blocks/SM interleave TMA and
// compute phases so DRAM never idles. Launched via PDL: TMA issue and
// exp/sid staging run before the grid dependency sync; only the denom
// division waits on k_exp. Compute: 12 float4-column-groups x 32 row-
// walkers from smem; red.v4 flush only at segment boundaries (seg sorted).
__global__ void __launch_bounds__(MAIN_THREADS, 4)
k_main(const float* __restrict__ a,
       const float* __restrict__ ft,
       const int* __restrict__ seg,
       float* __restrict__ out, int E) {
    extern __shared__ __align__(128) char smem[];
    float4* s_ft = (float4*)smem;
    float*  w_s  = (float*)(smem + SMEM_W_OFF);
    int*    s_s  = (int*)(smem + SMEM_S_OFF);
    uint32_t mb0 = smem_u32(smem + SMEM_MBAR_OFF);

    int base = blockIdx.x * CHUNK;
    int tid  = threadIdx.x;
    bool full = (base + CHUNK <= E);

    if (tid == 0) { mbar_init(mb0, 1); mbar_init(mb0 + 8, 1); }
    __syncthreads();

    if (full && tid == 0) {
        mbar_expect_tx(mb0, HALF_BYTES);
        bulk_g2s_stream(smem_u32(s_ft), ft + (size_t)base * DFEAT, HALF_BYTES, mb0);
        mbar_expect_tx(mb0 + 8, HALF_BYTES);
        bulk_g2s_stream(smem_u32(s_ft) + HALF_BYTES,
                        ft + (size_t)(base + HALF_ROWS) * DFEAT, HALF_BYTES, mb0 + 8);
    }

    // Stage exp(a) and sid (independent of k_exp's denominators)
    float ex = 0.0f;
    int   sid_t = -1;
    if (tid < CHUNK) {
        int e = base + tid;
        if (e < E) {
            sid_t = seg[e];
            ex = __expf(a[e]);
        }
        s_s[tid] = sid_t;
    }

    if (!full) {
        // Tail chunk: guarded per-thread loads into smem
        const float4* ft4 = (const float4*)ft;
        for (int i = tid; i < CHUNK * NCG; i += MAIN_THREADS) {
            int row = base + i / NCG;
            s_ft[i] = (row < E) ? ft4[(size_t)row * NCG + (i % NCG)]
                                : make_float4(0.f, 0.f, 0.f, 0.f);
        }
    }

#if __CUDA_ARCH__ >= 900
    cudaGridDependencySynchronize();   // k_exp (denom + out zero) complete
#endif

    if (tid < CHUNK)
        w_s[tid] = (sid_t >= 0) ? __fdividef(ex, g_denom[sid_t]) : 0.0f;

    __syncthreads();

    int cg = tid % NCG;            // float4 column group (0..11)
    int y  = tid / NCG;            // walker id (0..31)
    int j0 = y * WALKR;

    // Warps consuming rows [0,128) wait on mb0; rows [128,256) on mb1.
    if (full) mbar_wait(j0 < HALF_ROWS ? mb0 : mb0 + 8, 0);

    int    cur = s_s[j0];
    float4 acc = make_float4(0.f, 0.f, 0.f, 0.f);

    #pragma unroll
    for (int k = 0; k < WALKR; k++) {
        int j = j0 + k;
        int    sid = s_s[j];
        float  w   = w_s[j];
        float4 v   = s_ft[j * NCG + cg];
        if (sid != cur) {
            if (cur >= 0) red_add_v4(out + (size_t)cur * DFEAT + cg * 4, acc);
            acc = make_float4(0.f, 0.f, 0.f, 0.f);
            cur = sid;
        }
        acc.x += w * v.x;
        acc.y += w * v.y;
        acc.z += w * v.z;
        acc.w += w * v.w;
    }
    if (cur >= 0) red_add_v4(out + (size_t)cur * DFEAT + cg * 4, acc);
}

extern "C" void kernel_launch(void* const* d_in, const int* in_sizes, int n_in,
                              void* d_out, int out_size) {
    const float* a   = (const float*)d_in[0];
    const float* ft  = (const float*)d_in[1];
    const int*   seg = (const int*)d_in[2];
    float* out = (float*)d_out;

    int E = in_sizes[0];

    // Zero denominators directly on the device symbol (no kernel launch).
    void* denom_ptr = nullptr;
    cudaGetSymbolAddress(&denom_ptr, g_denom);
    cudaMemsetAsync(denom_ptr, 0, sizeof(g_denom));

    // k_exp also zeroes the output buffer (fused).
    int e8 = (E + 7) / 8;
    k_exp<<<(e8 + 255) / 256, 256>>>(a, seg, E, (float4*)out, out_size / 4);

    cudaFuncSetAttribute(k_main, cudaFuncAttributeMaxDynamicSharedMemorySize,
                         SMEM_TOTAL);
    int mb = (E + CHUNK - 1) / CHUNK;

    // PDL launch + L2 persisting window on out (red.v4 targets stay resident
    // while the ft stream floods L2 with evict_first sectors).
    cudaLaunchConfig_t cfg = {};
    cfg.gridDim = dim3(mb);
    cfg.blockDim = dim3(MAIN_THREADS);
    cfg.dynamicSmemBytes = SMEM_TOTAL;
    cudaLaunchAttribute attrs[2];
    attrs[0].id = cudaLaunchAttributeProgrammaticStreamSerialization;
    attrs[0].val.programmaticStreamSerializationAllowed = 1;
    attrs[1].id = cudaLaunchAttributeAccessPolicyWindow;
    attrs[1].val.accessPolicyWindow.base_ptr = out;
    attrs[1].val.accessPolicyWindow.num_bytes = (size_t)out_size * sizeof(float);
    attrs[1].val.accessPolicyWindow.hitRatio = 1.0f;
    attrs[1].val.accessPolicyWindow.hitProp = cudaAccessPropertyPersisting;
    attrs[1].val.accessPolicyWindow.missProp = cudaAccessPropertyStreaming;
    cfg.attrs = attrs;
    cfg.numAttrs = 2;
    cudaLaunchKernelEx(&cfg, k_main, a, ft, seg, out, E);
}